// round 9
// baseline (speedup 1.0000x reference)
#include <cuda_runtime.h>

// Problem constants
#define NLP 512   // scan length (up)
#define NLQ 512   // attention length (uq)
#define NB  24    // batch
#define NH  150   // hidden = in_size

// ---------------- device scratch (static allocation; no cudaMalloc) ----------------
__device__ float g_WUq[NLQ * NB * NH];     // uq @ Wq_eff.T, precomputed   (7.4MB)
__device__ float g_Wup[NLP * NB * NH];     // up @ Wp_eff.T, precomputed   (7.4MB)
__device__ float g_WqeT[NH * 160];         // WqeT[k*160+n] = Wq_eff[n][k]
__device__ float g_WpeT[NH * 160];
__device__ float g_WvT [NH * 160];         // WvT[d*160+h]  = Wv[h][d]
__device__ float g_WgAT[NH * 320];         // acts on up_i  (h < 300)
__device__ float g_WgCT[NH * 320];         // acts on c     (h < 300)
__device__ float g_wihT[300 * 480];        // wihT[j*480+k] = w_ih[k][j]
__device__ float g_whhT[NH * 480];         // whhT[d*480+k] = w_hh[k][d]

// Accurate fast tanh: 1 - 2/(e^{2x}+1).  EX2 + RCP (2 MUFU), rel err ~1e-7.
__device__ __forceinline__ float tanh_e(float x) {
    float t = __expf(2.0f * x);
    return 1.0f - __fdividef(2.0f, t + 1.0f);
}
__device__ __forceinline__ float sigm(float x) {
    return __fdividef(1.0f, 1.0f + __expf(-x));
}

// ---------------- prep: fold doubled columns + transpose all weights ----------------
__global__ void prep_kernel(const float* __restrict__ Wp, const float* __restrict__ Wq,
                            const float* __restrict__ Wv, const float* __restrict__ Wg,
                            const float* __restrict__ wih, const float* __restrict__ whh)
{
    int tid = blockIdx.x * blockDim.x + threadIdx.x;
    int nt  = gridDim.x * blockDim.x;

    for (int i = tid; i < 150 * 150; i += nt) {
        int k = i / 150, n = i - k * 150;
        g_WqeT[k * 160 + n] = Wq[n * 300 + k] + Wq[n * 300 + 150 + k];
        g_WpeT[k * 160 + n] = Wp[n * 300 + k] + Wp[n * 300 + 150 + k];
        g_WvT [k * 160 + n] = Wv[n * 150 + k];
    }
    for (int i = tid; i < 150 * 300; i += nt) {
        int d = i / 300, h = i - d * 300;
        const float* row = Wg + (300 + h) * 600;
        g_WgAT[d * 320 + h] = row[d]       + row[150 + d];
        g_WgCT[d * 320 + h] = row[300 + d] + row[450 + d];
    }
    for (int i = tid; i < 300 * 450; i += nt) {
        int j = i / 450, k = i - j * 450;
        g_wihT[j * 480 + k] = wih[k * 300 + j];
    }
    for (int i = tid; i < 150 * 450; i += nt) {
        int j = i / 450, k = i - j * 450;
        g_whhT[j * 480 + k] = whh[k * 150 + j];
    }
}

// ---------------- one-shot GEMM: C[M x 150] = A[M x 150] * B[150 x 150] ----------------
// which==0: A=uq, B=g_WqeT, C=g_WUq.  which==1: A=up, B=g_WpeT, C=g_Wup.
// Block: 160 threads, 16 rows per block. B rows stride 160 (128B aligned).
__global__ void __launch_bounds__(160) gemm150(const float* __restrict__ A, int which)
{
    __shared__ float As[16][152];
    const float* __restrict__ Bm = (which == 0) ? g_WqeT : g_WpeT;
    float* __restrict__ C        = (which == 0) ? g_WUq  : g_Wup;

    int row0 = blockIdx.x * 16;
    for (int i = threadIdx.x; i < 16 * 150; i += 160) {
        int r = i / 150, k = i - r * 150;
        As[r][k] = A[(row0 + r) * 150 + k];
    }
    __syncthreads();

    int n = threadIdx.x;
    if (n < 150) {
        #pragma unroll
        for (int r = 0; r < 16; r += 4) {
            float a0 = 0.f, a1 = 0.f, a2 = 0.f, a3 = 0.f;
            #pragma unroll 2
            for (int k = 0; k < 150; k++) {
                float bv = Bm[k * 160 + n];
                a0 += As[r + 0][k] * bv;
                a1 += As[r + 1][k] * bv;
                a2 += As[r + 2][k] * bv;
                a3 += As[r + 3][k] * bv;
            }
            C[(row0 + r + 0) * 150 + n] = a0;
            C[(row0 + r + 1) * 150 + n] = a1;
            C[(row0 + r + 2) * 150 + n] = a2;
            C[(row0 + r + 3) * 150 + n] = a3;
        }
    }
}

// ---------------- persistent per-batch recurrence: 24 CTAs x 1024 threads ----------------
__global__ void __launch_bounds__(1024, 1) pq_main(
    const float* __restrict__ up, const float* __restrict__ uq,
    const float* __restrict__ v0, const float* __restrict__ Vm,
    const float* __restrict__ b_ih, const float* __restrict__ b_hh,
    float* __restrict__ out)
{
    const int b    = blockIdx.x;
    const int tid  = threadIdx.x;
    const int warp = tid >> 5;
    const int lane = tid & 31;

    __shared__ float sv[152];      // GRU hidden v
    __shared__ float sVv[152];     // V[b,:,0]
    __shared__ float st[152];      // Wvv + Wup_i  (score bias per h)
    __shared__ float sup[152];     // up_i
    __shared__ float sc[152];      // context c
    __shared__ float sa[512];      // scores -> exp weights
    __shared__ float scp[4][152];  // context partials
    __shared__ float sc_[304];     // gated input c_
    __shared__ float sgh[456];     // v @ w_hh.T + b_hh
    __shared__ float sgi[2][464];  // c_ @ w_ih.T partials
    __shared__ float sred[32];
    __shared__ float sscal;

    if (tid < 150) {
        sv[tid]  = v0[b * 150 + tid];
        sVv[tid] = Vm[b * 150 + tid];
    }
    __syncthreads();

    for (int i = 0; i < NLP; i++) {
        const int rowi = (i * NB + b) * NH;

        // ---- Phase A: st = Wup_i + v@Wv.T ; sgh = v@w_hh.T + b_hh ; load up_i ----
        if (tid < 150) {
            int o = tid;
            float acc = g_Wup[rowi + o];
            float a0 = 0.f, a1 = 0.f;
            #pragma unroll 2
            for (int d = 0; d < 150; d += 2) {
                a0 += sv[d]     * g_WvT[d * 160 + o];
                a1 += sv[d + 1] * g_WvT[(d + 1) * 160 + o];
            }
            st[o] = acc + a0 + a1;
        } else if (tid >= 160 && tid < 310) {
            sup[tid - 160] = up[rowi + (tid - 160)];
        } else if (tid >= 512 && tid < 962) {
            int k = tid - 512;
            float a0 = b_hh[k], a1 = 0.f;
            #pragma unroll 2
            for (int d = 0; d < 150; d += 2) {
                a0 += sv[d]     * g_whhT[d * 480 + k];
                a1 += sv[d + 1] * g_whhT[(d + 1) * 480 + k];
            }
            sgh[k] = a0 + a1;
        }
        __syncthreads();

        // ---- Phase B: scores s[l] = sum_h Vv[h]*tanh(WUq[l,b,h] + st[h]) ----
        for (int l = warp; l < NLQ; l += 32) {
            const float* pq = g_WUq + (l * NB + b) * NH;
            float acc = 0.f;
            #pragma unroll
            for (int t = 0; t < 4; t++) {
                int h = lane + 32 * t;
                acc += sVv[h] * tanh_e(pq[h] + st[h]);
            }
            {
                int h = lane + 128;
                if (h < 150) acc += sVv[h] * tanh_e(pq[h] + st[h]);
            }
            #pragma unroll
            for (int o = 16; o > 0; o >>= 1)
                acc += __shfl_xor_sync(0xffffffffu, acc, o);
            if (lane == 0) sa[l] = acc;
        }
        __syncthreads();

        // ---- Phase C: softmax over l (max, exp-in-place, sum) ----
        {
            float vmax = (tid < 512) ? sa[tid] : -3.4e38f;
            #pragma unroll
            for (int o = 16; o > 0; o >>= 1)
                vmax = fmaxf(vmax, __shfl_xor_sync(0xffffffffu, vmax, o));
            if (lane == 0) sred[warp] = vmax;
            __syncthreads();
            if (tid < 32) {
                float v = sred[tid];
                #pragma unroll
                for (int o = 16; o > 0; o >>= 1)
                    v = fmaxf(v, __shfl_xor_sync(0xffffffffu, v, o));
                if (tid == 0) sscal = v;
            }
            __syncthreads();
            float mx = sscal;
            float e = 0.f;
            if (tid < 512) { e = __expf(sa[tid] - mx); sa[tid] = e; }
            #pragma unroll
            for (int o = 16; o > 0; o >>= 1)
                e += __shfl_xor_sync(0xffffffffu, e, o);
            if (lane == 0) sred[warp] = e;
            __syncthreads();
            if (tid < 32) {
                float v = sred[tid];
                #pragma unroll
                for (int o = 16; o > 0; o >>= 1)
                    v += __shfl_xor_sync(0xffffffffu, v, o);
                if (tid == 0) sscal = v;   // sum of exps
            }
            __syncthreads();
        }

        // ---- Phase D: context c[d] = (sum_l e[l]*uq[l,b,d]) / sum_e ----
        {
            int part = tid >> 8;       // 0..3, 128 l each
            int d    = tid & 255;
            if (d < 150) {
                const float* uqb = uq + b * NH + d;
                int l0 = part * 128;
                float a0 = 0.f, a1 = 0.f;
                #pragma unroll 2
                for (int l = l0; l < l0 + 128; l += 2) {
                    a0 += sa[l]     * uqb[l * (NB * NH)];
                    a1 += sa[l + 1] * uqb[(l + 1) * (NB * NH)];
                }
                scp[part][d] = a0 + a1;
            }
        }
        __syncthreads();
        if (tid < 150) {
            float inv = __fdividef(1.0f, sscal);
            sc[tid] = (scp[0][tid] + scp[1][tid] + scp[2][tid] + scp[3][tid]) * inv;
        }
        __syncthreads();

        // ---- Phase E: g2[h] = sigmoid(up_i@WgA + c@WgC) ; c_[h] = g2[h]*c[h%150] ----
        if (tid < 300) {
            int h = tid;
            float a0 = 0.f, a1 = 0.f;
            #pragma unroll 2
            for (int d = 0; d < 150; d += 2) {
                a0 += sup[d]     * g_WgAT[d * 320 + h]       + sc[d]     * g_WgCT[d * 320 + h];
                a1 += sup[d + 1] * g_WgAT[(d + 1) * 320 + h] + sc[d + 1] * g_WgCT[(d + 1) * 320 + h];
            }
            float g = sigm(a0 + a1);
            sc_[h] = g * sc[h < 150 ? h : h - 150];
        }
        __syncthreads();

        // ---- Phase F: gi = c_ @ w_ih.T + b_ih  (split K across 2 halves) ----
        {
            int part = tid >> 9;       // 0 or 1
            int k    = tid & 511;
            if (k < 450) {
                float a0 = (part == 0) ? b_ih[k] : 0.f;
                float a1 = 0.f;
                int j0 = part * 150;
                #pragma unroll 2
                for (int j = j0; j < j0 + 150; j += 2) {
                    a0 += sc_[j]     * g_wihT[j * 480 + k];
                    a1 += sc_[j + 1] * g_wihT[(j + 1) * 480 + k];
                }
                sgi[part][k] = a0 + a1;
            }
        }
        __syncthreads();

        // ---- Phase G: GRU gates, update v, write output ----
        if (tid < 150) {
            int k = tid;
            float gr = sgi[0][k]       + sgi[1][k]       + sgh[k];
            float gz = sgi[0][150 + k] + sgi[1][150 + k] + sgh[150 + k];
            float gn = sgi[0][300 + k] + sgi[1][300 + k];
            float r  = sigm(gr);
            float z  = sigm(gz);
            float n  = tanh_e(gn + r * sgh[300 + k]);
            float vn = (1.0f - z) * n + z * sv[k];
            out[rowi + k] = vn;
            sv[k] = vn;
        }
        __syncthreads();
    }
}

// ---------------- launch ----------------
extern "C" void kernel_launch(void* const* d_in, const int* in_sizes, int n_in,
                              void* d_out, int out_size)
{
    const float* up  = (const float*)d_in[0];
    const float* uq  = (const float*)d_in[1];
    const float* v0  = (const float*)d_in[2];
    const float* V   = (const float*)d_in[3];
    const float* Wp  = (const float*)d_in[4];
    const float* Wq  = (const float*)d_in[5];
    const float* Wv  = (const float*)d_in[6];
    const float* Wg  = (const float*)d_in[7];
    const float* wih = (const float*)d_in[8];
    const float* whh = (const float*)d_in[9];
    const float* bih = (const float*)d_in[10];
    const float* bhh = (const float*)d_in[11];
    float* out = (float*)d_out;

    prep_kernel<<<128, 256>>>(Wp, Wq, Wv, Wg, wih, whh);
    gemm150<<<(NLQ * NB) / 16, 160>>>(uq, 0);   // g_WUq
    gemm150<<<(NLP * NB) / 16, 160>>>(up, 1);   // g_Wup
    pq_main<<<NB, 1024>>>(up, uq, v0, V, bih, bhh, out);
}

// round 12
// speedup vs baseline: 2.4980x; 2.4980x over previous
#include <cuda_runtime.h>
#include <cstdint>

// Problem constants
#define NLP 512
#define NLQ 512
#define NB  24
#define NH  150
#define CS  4      // cluster size (CTAs per batch)
#define NT  512    // threads per CTA

// ---------------- device scratch ----------------
__device__ float g_WUq[NLQ * NB * NH];
__device__ float g_Wup[NLP * NB * NH];
__device__ float g_WqeT[NH * 160];
__device__ float g_WpeT[NH * 160];
__device__ float g_WvT [NH * 160];
__device__ float g_WgAT[NH * 320];
__device__ float g_WgCT[NH * 320];
__device__ float g_wihT[300 * 480];
__device__ float g_whhT[NH * 480];

__device__ __forceinline__ float tanh_e(float x) {
    float t = __expf(2.0f * x);
    return 1.0f - __fdividef(2.0f, t + 1.0f);
}
__device__ __forceinline__ float sigm(float x) {
    return __fdividef(1.0f, 1.0f + __expf(-x));
}

// DSMEM broadcast store: write val to the same smem offset in ALL cluster ranks.
// Uses mapa + st.shared::cluster (validated addressing pattern); reads stay local.
__device__ __forceinline__ void bcast4(float* p, float val) {
    uint32_t a = (uint32_t)__cvta_generic_to_shared(p);
    #pragma unroll
    for (int j = 0; j < CS; ++j) {
        uint32_t ra;
        asm volatile("mapa.shared::cluster.u32 %0, %1, %2;" : "=r"(ra) : "r"(a), "r"(j));
        asm volatile("st.shared::cluster.f32 [%0], %1;" :: "r"(ra), "f"(val) : "memory");
    }
}
#define CLUSTER_SYNC() do { \
    asm volatile("barrier.cluster.arrive.aligned;" ::: "memory"); \
    asm volatile("barrier.cluster.wait.aligned;" ::: "memory"); } while (0)

// ---------------- prep: fold doubled columns + transpose ----------------
__global__ void prep_kernel(const float* __restrict__ Wp, const float* __restrict__ Wq,
                            const float* __restrict__ Wv, const float* __restrict__ Wg,
                            const float* __restrict__ wih, const float* __restrict__ whh)
{
    int tid = blockIdx.x * blockDim.x + threadIdx.x;
    int nt  = gridDim.x * blockDim.x;

    for (int i = tid; i < 150 * 150; i += nt) {
        int k = i / 150, n = i - k * 150;
        g_WqeT[k * 160 + n] = Wq[n * 300 + k] + Wq[n * 300 + 150 + k];
        g_WpeT[k * 160 + n] = Wp[n * 300 + k] + Wp[n * 300 + 150 + k];
        g_WvT [k * 160 + n] = Wv[n * 150 + k];
    }
    for (int i = tid; i < 150 * 300; i += nt) {
        int d = i / 300, h = i - d * 300;
        const float* row = Wg + (300 + h) * 600;
        g_WgAT[d * 320 + h] = row[d]       + row[150 + d];
        g_WgCT[d * 320 + h] = row[300 + d] + row[450 + d];
    }
    for (int i = tid; i < 300 * 450; i += nt) {
        int j = i / 450, k = i - j * 450;
        g_wihT[j * 480 + k] = wih[k * 300 + j];
    }
    for (int i = tid; i < 150 * 450; i += nt) {
        int j = i / 450, k = i - j * 450;
        g_whhT[j * 480 + k] = whh[k * 150 + j];
    }
}

// ---------------- one-shot GEMM (unchanged from passing R9) ----------------
__global__ void __launch_bounds__(160) gemm150(const float* __restrict__ A, int which)
{
    __shared__ float As[16][152];
    const float* __restrict__ Bm = (which == 0) ? g_WqeT : g_WpeT;
    float* __restrict__ C        = (which == 0) ? g_WUq  : g_Wup;

    int row0 = blockIdx.x * 16;
    for (int i = threadIdx.x; i < 16 * 150; i += 160) {
        int r = i / 150, k = i - r * 150;
        As[r][k] = A[(row0 + r) * 150 + k];
    }
    __syncthreads();

    int n = threadIdx.x;
    if (n < 150) {
        #pragma unroll
        for (int r = 0; r < 16; r += 4) {
            float a0 = 0.f, a1 = 0.f, a2 = 0.f, a3 = 0.f;
            #pragma unroll 2
            for (int k = 0; k < 150; k++) {
                float bv = Bm[k * 160 + n];
                a0 += As[r + 0][k] * bv;
                a1 += As[r + 1][k] * bv;
                a2 += As[r + 2][k] * bv;
                a3 += As[r + 3][k] * bv;
            }
            C[(row0 + r + 0) * 150 + n] = a0;
            C[(row0 + r + 1) * 150 + n] = a1;
            C[(row0 + r + 2) * 150 + n] = a2;
            C[(row0 + r + 3) * 150 + n] = a3;
        }
    }
}

// ---------------- dynamic smem layout (all buffers replicated per rank) ----------------
struct SM {
    float WUq[128 * 150];   // local l-slice of uq@Wq   (76.8 KB)
    float Wih[300 * 113];   // local k-slice of w_ih^T  (135.6 KB)
    float st[152];          // full, filled by broadcast
    float gh[456];          // full, filled by broadcast (pre-S4)
    float gi[456];          // full, filled by broadcast
    float ghloc[116];       // local gh slice, held until pre-S4 broadcast
    float cc[304];          // full, filled by broadcast
    float msum[CS][2];      // per-rank {max, sum}, broadcast
    float cpart[CS][152];   // per-rank context partials, broadcast
    float v[152];           // GRU hidden (identical on all ranks)
    float Vv[152];
    float c[152];
    float sup[152];
    float sa[128];
    float red[16];
    float scratch[512];
};

// ---------------- per-batch cluster recurrence: 24 clusters x 4 CTAs ----------------
__global__ void __launch_bounds__(NT, 1) __cluster_dims__(CS, 1, 1)
pq_main(const float* __restrict__ up, const float* __restrict__ uq,
        const float* __restrict__ v0, const float* __restrict__ Vm,
        const float* __restrict__ b_ih, const float* __restrict__ b_hh,
        float* __restrict__ out)
{
    extern __shared__ char smem_raw[];
    SM* s = (SM*)smem_raw;

    const int b    = blockIdx.x / CS;
    const int r    = blockIdx.x % CS;     // == cluster rank (cluster dims (4,1,1))
    const int tid  = threadIdx.x;
    const int warp = tid >> 5;
    const int lane = tid & 31;

    const int l0  = r * 128;                                  // l-slice
    const int hA0 = (150 * r) / CS, hw = (150 * (r + 1)) / CS - hA0;   // st slice (37/38)
    const int kB0 = (450 * r) / CS, kw = (450 * (r + 1)) / CS - kB0;   // gh/gi slice (112/113)

    // ---- init: cache slices in smem ----
    for (int idx = tid; idx < 128 * 150; idx += NT) {
        int l = idx / 150, h = idx - l * 150;
        s->WUq[idx] = g_WUq[((l0 + l) * NB + b) * 150 + h];
    }
    for (int idx = tid; idx < 300 * 113; idx += NT) {
        int j = idx / 113, kl = idx - j * 113;
        s->Wih[idx] = (kl < kw) ? g_wihT[j * 480 + kB0 + kl] : 0.f;
    }
    if (tid < 150) {
        s->v[tid]  = v0[b * 150 + tid];
        s->Vv[tid] = Vm[b * 150 + tid];
    }
    CLUSTER_SYNC();

    for (int i = 0; i < NLP; i++) {
        const int rowi = (i * NB + b) * NH;

        // ======== Phase A: st h-slice (v@Wv + Wup) and gh k-slice (v@whh + b_hh) ========
        for (int x = tid; x < 150; x += NT) s->sup[x] = up[rowi + x];

        if (tid < 152) {                       // st partials: 38 h x 4 d-parts
            int hl = tid % 38, dp = tid / 38;
            float a = 0.f;
            if (hl < hw) {
                int d0 = dp * 38, d1 = (d0 + 38 < 150) ? d0 + 38 : 150;
                int hg = hA0 + hl;
                #pragma unroll 4
                for (int d = d0; d < d1; ++d)
                    a += s->v[d] * g_WvT[d * 160 + hg];
            }
            s->scratch[tid] = a;
        } else if (tid < 491) {                // gh partials: 113 k x 3 d-parts of 50
            int t = tid - 152;
            int kl = t % 113, dp = t / 113;
            float a = 0.f;
            if (kl < kw) {
                int d0 = dp * 50;
                int kg = kB0 + kl;
                #pragma unroll 5
                for (int d = d0; d < d0 + 50; ++d)
                    a += s->v[d] * g_whhT[d * 480 + kg];
            }
            s->scratch[tid] = a;
        }
        __syncthreads();
        if (tid < hw) {
            int hg = hA0 + tid;
            float a = g_Wup[rowi + hg] + s->scratch[tid] + s->scratch[38 + tid]
                    + s->scratch[76 + tid] + s->scratch[114 + tid];
            bcast4(&s->st[hg], a);
        } else if (tid >= 64 && tid < 64 + kw) {
            int kl = tid - 64;
            s->ghloc[kl] = b_hh[kB0 + kl] + s->scratch[152 + kl]
                         + s->scratch[265 + kl] + s->scratch[378 + kl];
        }
        CLUSTER_SYNC();                                       // S1: st full everywhere

        // ======== Phase B: scores over local 128-l slice ========
        for (int l = warp; l < 128; l += 16) {
            const float* row = s->WUq + l * 150;
            float acc = 0.f;
            #pragma unroll
            for (int t4 = 0; t4 < 4; t4++) {
                int h = lane + 32 * t4;
                acc += s->Vv[h] * tanh_e(row[h] + s->st[h]);
            }
            {
                int h = lane + 128;
                if (h < 150) acc += s->Vv[h] * tanh_e(row[h] + s->st[h]);
            }
            #pragma unroll
            for (int o = 16; o > 0; o >>= 1)
                acc += __shfl_xor_sync(0xffffffffu, acc, o);
            if (lane == 0) s->sa[l] = acc;
        }
        __syncthreads();

        // local max
        if (tid < 128) {
            float m = s->sa[tid];
            #pragma unroll
            for (int o = 16; o > 0; o >>= 1)
                m = fmaxf(m, __shfl_xor_sync(0xffffffffu, m, o));
            if (lane == 0) s->red[warp] = m;
        }
        __syncthreads();
        if (tid == 0)
            s->red[8] = fmaxf(fmaxf(s->red[0], s->red[1]), fmaxf(s->red[2], s->red[3]));
        __syncthreads();
        float mx = s->red[8];
        // exp + local sum
        if (tid < 128) {
            float e = __expf(s->sa[tid] - mx);
            s->sa[tid] = e;
            #pragma unroll
            for (int o = 16; o > 0; o >>= 1)
                e += __shfl_xor_sync(0xffffffffu, e, o);
            if (lane == 0) s->red[warp] = e;
        }
        __syncthreads();
        if (tid == 0) s->red[9] = s->red[0] + s->red[1] + s->red[2] + s->red[3];

        // context partial over local l's (uq streamed from L2, coalesced over d)
        if (tid < 450) {
            int part = tid / 150, d = tid - part * 150;
            int lpa = part * 43, lpb = (part == 2) ? 128 : lpa + 43;
            const float* uqp = uq + (size_t)(l0 * NB + b) * NH + d;
            float a0 = 0.f, a1 = 0.f;
            int l = lpa;
            for (; l + 1 < lpb; l += 2) {
                a0 += s->sa[l]     * uqp[(size_t)l       * (NB * NH)];
                a1 += s->sa[l + 1] * uqp[(size_t)(l + 1) * (NB * NH)];
            }
            if (l < lpb) a0 += s->sa[l] * uqp[(size_t)l * (NB * NH)];
            s->scratch[part * 152 + d] = a0 + a1;
        }
        __syncthreads();
        if (tid < 150) {
            float cp = s->scratch[tid] + s->scratch[152 + tid] + s->scratch[304 + tid];
            bcast4(&s->cpart[r][tid], cp);
        } else if (tid == 160) {
            bcast4(&s->msum[r][0], s->red[8]);
            bcast4(&s->msum[r][1], s->red[9]);
        }
        CLUSTER_SYNC();                                       // S2: cpart+msum everywhere

        // ======== Phase C: merge split-softmax -> full context (redundant per rank) ========
        if (tid < 150) {
            float M = s->msum[0][0];
            #pragma unroll
            for (int j = 1; j < CS; ++j) M = fmaxf(M, s->msum[j][0]);
            float gs = 0.f, acc = 0.f;
            #pragma unroll
            for (int j = 0; j < CS; ++j) {
                float w = __expf(s->msum[j][0] - M);
                gs  += w * s->msum[j][1];
                acc += w * s->cpart[j][tid];
            }
            s->c[tid] = __fdividef(acc, gs);
        }
        __syncthreads();

        // ======== Phase E: gate slice (75 h per rank) ========
        if (tid < 450) {
            int hl = tid % 75, dp = tid / 75;   // 6 d-parts of 25
            int hg = 75 * r + hl;
            int d0 = dp * 25;
            float a = 0.f;
            #pragma unroll 5
            for (int d = d0; d < d0 + 25; ++d)
                a += s->sup[d] * g_WgAT[d * 320 + hg] + s->c[d] * g_WgCT[d * 320 + hg];
            s->scratch[dp * 75 + hl] = a;
        }
        __syncthreads();
        if (tid < 75) {
            float a = s->scratch[tid]       + s->scratch[75 + tid]  + s->scratch[150 + tid]
                    + s->scratch[225 + tid] + s->scratch[300 + tid] + s->scratch[375 + tid];
            int hg = 75 * r + tid;
            float g = sigm(a);
            bcast4(&s->cc[hg], g * s->c[(hg < 150) ? hg : hg - 150]);
        }
        CLUSTER_SYNC();                                       // S3: cc everywhere

        // ======== Phase F: gi k-slice from smem-cached w_ih ========
        if (tid < 452) {
            int kl = tid % 113, jp = tid / 113; // 4 j-parts of 75
            float a = 0.f;
            if (kl < kw) {
                int j0 = jp * 75;
                #pragma unroll 5
                for (int j = j0; j < j0 + 75; ++j)
                    a += s->cc[j] * s->Wih[j * 113 + kl];
            }
            s->scratch[jp * 113 + kl] = a;
        }
        __syncthreads();
        if (tid < kw) {
            float a = b_ih[kB0 + tid] + s->scratch[tid] + s->scratch[113 + tid]
                    + s->scratch[226 + tid] + s->scratch[339 + tid];
            bcast4(&s->gi[kB0 + tid], a);
        } else if (tid >= 128 && tid < 128 + kw) {
            int kl = tid - 128;
            bcast4(&s->gh[kB0 + kl], s->ghloc[kl]);           // delayed gh broadcast
        }
        CLUSTER_SYNC();                                       // S4: gi+gh everywhere

        // ======== Phase G: GRU update (redundant full per rank; rank 0 writes out) ========
        if (tid < 150) {
            float gr = s->gi[tid]       + s->gh[tid];
            float gz = s->gi[150 + tid] + s->gh[150 + tid];
            float gn = s->gi[300 + tid];
            float hn = s->gh[300 + tid];
            float rr = sigm(gr);
            float zz = sigm(gz);
            float nn = tanh_e(gn + rr * hn);
            float vn = (1.0f - zz) * nn + zz * s->v[tid];
            if (r == 0) out[rowi + tid] = vn;
            s->v[tid] = vn;
        }
        __syncthreads();
    }
}

// ---------------- launch ----------------
extern "C" void kernel_launch(void* const* d_in, const int* in_sizes, int n_in,
                              void* d_out, int out_size)
{
    const float* up  = (const float*)d_in[0];
    const float* uq  = (const float*)d_in[1];
    const float* v0  = (const float*)d_in[2];
    const float* V   = (const float*)d_in[3];
    const float* Wp  = (const float*)d_in[4];
    const float* Wq  = (const float*)d_in[5];
    const float* Wv  = (const float*)d_in[6];
    const float* Wg  = (const float*)d_in[7];
    const float* wih = (const float*)d_in[8];
    const float* whh = (const float*)d_in[9];
    const float* bih = (const float*)d_in[10];
    const float* bhh = (const float*)d_in[11];
    float* out = (float*)d_out;

    cudaFuncSetAttribute(pq_main, cudaFuncAttributeMaxDynamicSharedMemorySize,
                         (int)sizeof(SM));

    prep_kernel<<<128, 256>>>(Wp, Wq, Wv, Wg, wih, whh);
    gemm150<<<(NLQ * NB) / 16, 160>>>(uq, 0);   // g_WUq
    gemm150<<<(NLP * NB) / 16, 160>>>(up, 1);   // g_Wup
    pq_main<<<NB * CS, NT, sizeof(SM)>>>(up, uq, v0, V, bih, bhh, out);
}

// round 13
// speedup vs baseline: 2.8162x; 1.1274x over previous
#include <cuda_runtime.h>
#include <cstdint>

// Problem constants
#define NLP 512
#define NLQ 512
#define NB  24
#define NH  150
#define CS  4      // cluster size (CTAs per batch)
#define NT  1024   // threads per CTA

// ---------------- device scratch ----------------
__device__ float g_WUq[NLQ * NB * NH];
__device__ float g_Wup[NLP * NB * NH];
__device__ float g_WqeT[NH * 160];
__device__ float g_WpeT[NH * 160];
__device__ float g_WvT [NH * 160];
__device__ float g_WgAT[NH * 320];
__device__ float g_WgCT[NH * 320];
__device__ float g_wihT[300 * 480];
__device__ float g_whhT[NH * 480];

__device__ __forceinline__ float tanh_e(float x) {
    float t = __expf(2.0f * x);
    return 1.0f - __fdividef(2.0f, t + 1.0f);
}
__device__ __forceinline__ float sigm(float x) {
    return __fdividef(1.0f, 1.0f + __expf(-x));
}

// DSMEM broadcast store: write val to same smem offset in ALL cluster ranks.
__device__ __forceinline__ void bcast4(float* p, float val) {
    uint32_t a = (uint32_t)__cvta_generic_to_shared(p);
    #pragma unroll
    for (int j = 0; j < CS; ++j) {
        uint32_t ra;
        asm volatile("mapa.shared::cluster.u32 %0, %1, %2;" : "=r"(ra) : "r"(a), "r"(j));
        asm volatile("st.shared::cluster.f32 [%0], %1;" :: "r"(ra), "f"(val) : "memory");
    }
}
#define CLUSTER_SYNC() do { \
    asm volatile("barrier.cluster.arrive.aligned;" ::: "memory"); \
    asm volatile("barrier.cluster.wait.aligned;" ::: "memory"); } while (0)

// ---------------- prep ----------------
__global__ void prep_kernel(const float* __restrict__ Wp, const float* __restrict__ Wq,
                            const float* __restrict__ Wv, const float* __restrict__ Wg,
                            const float* __restrict__ wih, const float* __restrict__ whh)
{
    int tid = blockIdx.x * blockDim.x + threadIdx.x;
    int nt  = gridDim.x * blockDim.x;

    for (int i = tid; i < 150 * 150; i += nt) {
        int k = i / 150, n = i - k * 150;
        g_WqeT[k * 160 + n] = Wq[n * 300 + k] + Wq[n * 300 + 150 + k];
        g_WpeT[k * 160 + n] = Wp[n * 300 + k] + Wp[n * 300 + 150 + k];
        g_WvT [k * 160 + n] = Wv[n * 150 + k];
    }
    for (int i = tid; i < 150 * 300; i += nt) {
        int d = i / 300, h = i - d * 300;
        const float* row = Wg + (300 + h) * 600;
        g_WgAT[d * 320 + h] = row[d]       + row[150 + d];
        g_WgCT[d * 320 + h] = row[300 + d] + row[450 + d];
    }
    for (int i = tid; i < 300 * 450; i += nt) {
        int j = i / 450, k = i - j * 450;
        g_wihT[j * 480 + k] = wih[k * 300 + j];
    }
    for (int i = tid; i < 150 * 450; i += nt) {
        int j = i / 450, k = i - j * 450;
        g_whhT[j * 480 + k] = whh[k * 150 + j];
    }
}

// ---------------- one-shot GEMM (unchanged) ----------------
__global__ void __launch_bounds__(160) gemm150(const float* __restrict__ A, int which)
{
    __shared__ float As[16][152];
    const float* __restrict__ Bm = (which == 0) ? g_WqeT : g_WpeT;
    float* __restrict__ C        = (which == 0) ? g_WUq  : g_Wup;

    int row0 = blockIdx.x * 16;
    for (int i = threadIdx.x; i < 16 * 150; i += 160) {
        int r = i / 150, k = i - r * 150;
        As[r][k] = A[(row0 + r) * 150 + k];
    }
    __syncthreads();

    int n = threadIdx.x;
    if (n < 150) {
        #pragma unroll
        for (int r = 0; r < 16; r += 4) {
            float a0 = 0.f, a1 = 0.f, a2 = 0.f, a3 = 0.f;
            #pragma unroll 2
            for (int k = 0; k < 150; k++) {
                float bv = Bm[k * 160 + n];
                a0 += As[r + 0][k] * bv;
                a1 += As[r + 1][k] * bv;
                a2 += As[r + 2][k] * bv;
                a3 += As[r + 3][k] * bv;
            }
            C[(row0 + r + 0) * 150 + n] = a0;
            C[(row0 + r + 1) * 150 + n] = a1;
            C[(row0 + r + 2) * 150 + n] = a2;
            C[(row0 + r + 3) * 150 + n] = a3;
        }
    }
}

// ---------------- dynamic smem layout ----------------
struct SM {
    float WUq[128 * 150];   // local l-slice of uq@Wq   (76.8 KB)
    float Wih[300 * 113];   // local k-slice of w_ih^T  (135.6 KB)
    float st[152];
    float gh[456];
    float gi[456];
    float ghloc[116];
    float cc[304];
    float msum[CS][2];
    float cpart[CS][152];
    float v[152];
    float Vv[152];
    float c[152];
    float sup[152];
    float sa[128];
    float red[16];
    float scratch[960];
};

// ---------------- per-batch cluster recurrence: 24 clusters x 4 CTAs x 1024 thr ----------------
__global__ void __launch_bounds__(NT, 1) __cluster_dims__(CS, 1, 1)
pq_main(const float* __restrict__ up, const float* __restrict__ uq,
        const float* __restrict__ v0, const float* __restrict__ Vm,
        const float* __restrict__ b_ih, const float* __restrict__ b_hh,
        float* __restrict__ out)
{
    extern __shared__ char smem_raw[];
    SM* s = (SM*)smem_raw;

    const int b    = blockIdx.x / CS;
    const int r    = blockIdx.x % CS;
    const int tid  = threadIdx.x;
    const int warp = tid >> 5;
    const int lane = tid & 31;

    const int l0  = r * 128;
    const int hA0 = (150 * r) / CS, hw = (150 * (r + 1)) / CS - hA0;   // 37/38
    const int kB0 = (450 * r) / CS, kw = (450 * (r + 1)) / CS - kB0;   // 112/113

    // ---- init: cache slices ----
    for (int idx = tid; idx < 128 * 150; idx += NT) {
        int l = idx / 150, h = idx - l * 150;
        s->WUq[idx] = g_WUq[((l0 + l) * NB + b) * 150 + h];
    }
    for (int idx = tid; idx < 300 * 113; idx += NT) {
        int j = idx / 113, kl = idx - j * 113;
        s->Wih[idx] = (kl < kw) ? g_wihT[j * 480 + kB0 + kl] : 0.f;
    }
    if (tid < 150) {
        s->v[tid]  = v0[b * 150 + tid];
        s->Vv[tid] = Vm[b * 150 + tid];
    }
    CLUSTER_SYNC();

    for (int i = 0; i < NLP; i++) {
        const int rowi = (i * NB + b) * NH;

        // ======== Phase A: st h-slice (v@Wv + Wup), gh k-slice (v@whh + b_hh) ========
        if (tid < 150) s->sup[tid] = up[rowi + tid];

        if (tid < 380) {                        // st partials: 38 h x 10 d-parts of 15
            int hl = tid % 38, dp = tid / 38;
            float a = 0.f;
            if (hl < hw) {
                int hg = hA0 + hl;
                int d0 = dp * 15;
                #pragma unroll
                for (int d = d0; d < d0 + 15; ++d)
                    a += s->v[d] * g_WvT[d * 160 + hg];
            }
            s->scratch[tid] = a;
        } else if (tid >= 384 && tid < 949) {   // gh partials: 113 k x 5 d-parts of 30
            int t = tid - 384;
            int kl = t % 113, dp = t / 113;
            float a = 0.f;
            if (kl < kw) {
                int kg = kB0 + kl;
                int d0 = dp * 30;
                #pragma unroll 6
                for (int d = d0; d < d0 + 30; ++d)
                    a += s->v[d] * g_whhT[d * 480 + kg];
            }
            s->scratch[tid] = a;
        }
        __syncthreads();
        if (tid < hw) {
            int hg = hA0 + tid;
            float a = g_Wup[rowi + hg];
            #pragma unroll
            for (int dp = 0; dp < 10; ++dp) a += s->scratch[dp * 38 + tid];
            bcast4(&s->st[hg], a);
        } else if (tid >= 64 && tid < 64 + 113) {
            int kl = tid - 64;
            if (kl < kw) {
                float a = b_hh[kB0 + kl];
                #pragma unroll
                for (int dp = 0; dp < 5; ++dp) a += s->scratch[384 + dp * 113 + kl];
                s->ghloc[kl] = a;
            }
        }
        CLUSTER_SYNC();                                       // S1: st full everywhere

        // ======== Phase B: scores over local 128-l slice (32 warps, 4 l each) ========
        for (int l = warp; l < 128; l += 32) {
            const float* row = s->WUq + l * 150;
            float acc = 0.f;
            #pragma unroll
            for (int t4 = 0; t4 < 4; t4++) {
                int h = lane + 32 * t4;
                acc += s->Vv[h] * tanh_e(row[h] + s->st[h]);
            }
            {
                int h = lane + 128;
                if (h < 150) acc += s->Vv[h] * tanh_e(row[h] + s->st[h]);
            }
            #pragma unroll
            for (int o = 16; o > 0; o >>= 1)
                acc += __shfl_xor_sync(0xffffffffu, acc, o);
            if (lane == 0) s->sa[l] = acc;
        }
        __syncthreads();

        // local max
        if (tid < 128) {
            float m = s->sa[tid];
            #pragma unroll
            for (int o = 16; o > 0; o >>= 1)
                m = fmaxf(m, __shfl_xor_sync(0xffffffffu, m, o));
            if (lane == 0) s->red[warp] = m;
        }
        __syncthreads();
        if (tid == 0)
            s->red[8] = fmaxf(fmaxf(s->red[0], s->red[1]), fmaxf(s->red[2], s->red[3]));
        __syncthreads();
        float mx = s->red[8];
        // exp + local sum
        if (tid < 128) {
            float e = __expf(s->sa[tid] - mx);
            s->sa[tid] = e;
            #pragma unroll
            for (int o = 16; o > 0; o >>= 1)
                e += __shfl_xor_sync(0xffffffffu, e, o);
            if (lane == 0) s->red[warp] = e;
        }
        __syncthreads();
        if (tid == 0) s->red[9] = s->red[0] + s->red[1] + s->red[2] + s->red[3];

        // context partials: 4 l-parts of 32, 150 d each, unroll 8 (high MLP)
        if (tid < 600) {
            int part = tid / 150, d = tid - part * 150;
            int lpa = part * 32;
            const float* uqp = uq + (size_t)((l0 + lpa) * NB + b) * NH + d;
            float a0 = 0.f, a1 = 0.f, a2 = 0.f, a3 = 0.f;
            #pragma unroll 2
            for (int l = 0; l < 32; l += 8) {
                a0 += s->sa[lpa + l + 0] * uqp[(size_t)(l + 0) * (NB * NH)];
                a1 += s->sa[lpa + l + 1] * uqp[(size_t)(l + 1) * (NB * NH)];
                a2 += s->sa[lpa + l + 2] * uqp[(size_t)(l + 2) * (NB * NH)];
                a3 += s->sa[lpa + l + 3] * uqp[(size_t)(l + 3) * (NB * NH)];
                a0 += s->sa[lpa + l + 4] * uqp[(size_t)(l + 4) * (NB * NH)];
                a1 += s->sa[lpa + l + 5] * uqp[(size_t)(l + 5) * (NB * NH)];
                a2 += s->sa[lpa + l + 6] * uqp[(size_t)(l + 6) * (NB * NH)];
                a3 += s->sa[lpa + l + 7] * uqp[(size_t)(l + 7) * (NB * NH)];
            }
            s->scratch[part * 152 + d] = (a0 + a1) + (a2 + a3);
        }
        __syncthreads();
        if (tid < 150) {
            float cp = s->scratch[tid] + s->scratch[152 + tid]
                     + s->scratch[304 + tid] + s->scratch[456 + tid];
            bcast4(&s->cpart[r][tid], cp);
        } else if (tid == 160) {
            bcast4(&s->msum[r][0], s->red[8]);
            bcast4(&s->msum[r][1], s->red[9]);
        }
        CLUSTER_SYNC();                                       // S2

        // ======== Phase C: merge split-softmax -> context (redundant per rank) ========
        if (tid < 150) {
            float M = s->msum[0][0];
            #pragma unroll
            for (int j = 1; j < CS; ++j) M = fmaxf(M, s->msum[j][0]);
            float gs = 0.f, acc = 0.f;
            #pragma unroll
            for (int j = 0; j < CS; ++j) {
                float w = __expf(s->msum[j][0] - M);
                gs  += w * s->msum[j][1];
                acc += w * s->cpart[j][tid];
            }
            s->c[tid] = __fdividef(acc, gs);
        }
        __syncthreads();

        // ======== Phase E: gate slice (75 h x 10 d-parts of 15) ========
        if (tid < 750) {
            int hl = tid % 75, dp = tid / 75;
            int hg = 75 * r + hl;
            int d0 = dp * 15;
            float a = 0.f;
            #pragma unroll
            for (int d = d0; d < d0 + 15; ++d)
                a += s->sup[d] * g_WgAT[d * 320 + hg] + s->c[d] * g_WgCT[d * 320 + hg];
            s->scratch[dp * 75 + hl] = a;
        }
        __syncthreads();
        if (tid < 75) {
            float a = 0.f;
            #pragma unroll
            for (int dp = 0; dp < 10; ++dp) a += s->scratch[dp * 75 + tid];
            int hg = 75 * r + tid;
            float g = sigm(a);
            bcast4(&s->cc[hg], g * s->c[(hg < 150) ? hg : hg - 150]);
        }
        CLUSTER_SYNC();                                       // S3

        // ======== Phase F: gi k-slice (113 k x 6 j-parts of 50, smem weights) ========
        if (tid < 678) {
            int kl = tid % 113, jp = tid / 113;
            float a = 0.f;
            if (kl < kw) {
                int j0 = jp * 50;
                #pragma unroll 10
                for (int j = j0; j < j0 + 50; ++j)
                    a += s->cc[j] * s->Wih[j * 113 + kl];
            }
            s->scratch[jp * 113 + kl] = a;
        }
        __syncthreads();
        if (tid < kw) {
            float a = b_ih[kB0 + tid];
            #pragma unroll
            for (int jp = 0; jp < 6; ++jp) a += s->scratch[jp * 113 + tid];
            bcast4(&s->gi[kB0 + tid], a);
        } else if (tid >= 128 && tid < 128 + kw) {
            int kl = tid - 128;
            bcast4(&s->gh[kB0 + kl], s->ghloc[kl]);
        }
        CLUSTER_SYNC();                                       // S4

        // ======== Phase G: GRU update (redundant; rank 0 writes out) ========
        if (tid < 150) {
            float gr = s->gi[tid]       + s->gh[tid];
            float gz = s->gi[150 + tid] + s->gh[150 + tid];
            float gn = s->gi[300 + tid];
            float hn = s->gh[300 + tid];
            float rr = sigm(gr);
            float zz = sigm(gz);
            float nn = tanh_e(gn + rr * hn);
            float vn = (1.0f - zz) * nn + zz * s->v[tid];
            if (r == 0) out[rowi + tid] = vn;
            s->v[tid] = vn;
        }
        __syncthreads();
    }
}

// ---------------- launch ----------------
extern "C" void kernel_launch(void* const* d_in, const int* in_sizes, int n_in,
                              void* d_out, int out_size)
{
    const float* up  = (const float*)d_in[0];
    const float* uq  = (const float*)d_in[1];
    const float* v0  = (const float*)d_in[2];
    const float* V   = (const float*)d_in[3];
    const float* Wp  = (const float*)d_in[4];
    const float* Wq  = (const float*)d_in[5];
    const float* Wv  = (const float*)d_in[6];
    const float* Wg  = (const float*)d_in[7];
    const float* wih = (const float*)d_in[8];
    const float* whh = (const float*)d_in[9];
    const float* bih = (const float*)d_in[10];
    const float* bhh = (const float*)d_in[11];
    float* out = (float*)d_out;

    cudaFuncSetAttribute(pq_main, cudaFuncAttributeMaxDynamicSharedMemorySize,
                         (int)sizeof(SM));

    prep_kernel<<<128, 256>>>(Wp, Wq, Wv, Wg, wih, whh);
    gemm150<<<(NLQ * NB) / 16, 160>>>(uq, 0);   // g_WUq
    gemm150<<<(NLP * NB) / 16, 160>>>(up, 1);   // g_Wup
    pq_main<<<NB * CS, NT, sizeof(SM)>>>(up, uq, v0, V, bih, bhh, out);
}